// round 5
// baseline (speedup 1.0000x reference)
#include <cuda_runtime.h>
#include <math.h>

#define BATCH 512
#define INDIM 256
#define HIDD  512
#define HID2  256
#define PAT   10

typedef unsigned long long u64;

// -------- scratch (no allocations allowed) --------
__device__ __align__(128) float g_H [BATCH * HIDD];
__device__ __align__(128) float g_H2[BATCH * HID2];
__device__ __align__(128) float g_A [BATCH * HIDD];
__device__ __align__(128) float g_C [BATCH * HIDD];

// ---------- packed f32x2 helpers (sm_103a) ----------
__device__ __forceinline__ u64 pack2(float lo, float hi) {
    u64 r; asm("mov.b64 %0, {%1, %2};" : "=l"(r) : "f"(lo), "f"(hi)); return r;
}
__device__ __forceinline__ void unpack2(u64 v, float& lo, float& hi) {
    asm("mov.b64 {%0, %1}, %2;" : "=f"(lo), "=f"(hi) : "l"(v));
}
__device__ __forceinline__ u64 ffma2(u64 a, u64 b, u64 c) {
    u64 d; asm("fma.rn.f32x2 %0, %1, %2, %3;" : "=l"(d) : "l"(a), "l"(b), "l"(c)); return d;
}
__device__ __forceinline__ u64 dup2(float v) { return pack2(v, v); }

// ============================================================
// Launch 1: fused triple GEMM over shared X tile.
//   H = BN(x@W1^T + b1) relu ; A = x@Wa^T ; C = x@Wb^T + bs1
// Tile 32m x 32n, 128 threads, microtile 2m x 4n per matrix.
// X smem loaded ONCE per chunk, used by 3 weight planes.
// Double-buffered, 1 barrier per 16-deep K chunk.
// smem: [buf][plane(X,W1,Wa,Wb)][16][32] = 2*4*512 floats = 16KB
// ============================================================
__global__ __launch_bounds__(128)
void k_proj3(const float* __restrict__ x,
             const float* __restrict__ W1, const float* __restrict__ b1,
             const float* __restrict__ gam, const float* __restrict__ bet,
             const float* __restrict__ mean, const float* __restrict__ var,
             const float* __restrict__ Wa, const float* __restrict__ Wb,
             const float* __restrict__ bs1)
{
    __shared__ __align__(16) float sm[2][4][512];   // [buf][plane][k*32+row]

    const int t   = threadIdx.x;
    const int m0  = blockIdx.y * 32;
    const int n0  = blockIdx.x * 32;

    const int txn = t & 7;       // n quad: n = n0 + txn*4
    const int tym = t >> 3;      // m pair: m = m0 + tym*2   (0..15)

    const int row = t & 31;      // loader row
    const int kq  = t >> 5;      // 0..3 -> k offsets kq*4

    const float* Xg  = x  + (size_t)(m0 + row) * INDIM + kq * 4;
    const float* W1g = W1 + (size_t)(n0 + row) * INDIM + kq * 4;
    const float* Wag = Wa + (size_t)(n0 + row) * INDIM + kq * 4;
    const float* Wbg = Wb + (size_t)(n0 + row) * INDIM + kq * 4;

    u64 ac1[2][2], aca[2][2], acb[2][2];
#pragma unroll
    for (int r = 0; r < 2; r++)
#pragma unroll
        for (int c = 0; c < 2; c++) { ac1[r][c] = 0ull; aca[r][c] = 0ull; acb[r][c] = 0ull; }

    // prefetch chunk 0
    float4 xv  = *(const float4*)(Xg);
    float4 w1v = *(const float4*)(W1g);
    float4 wav = *(const float4*)(Wag);
    float4 wbv = *(const float4*)(Wbg);

    const int NC = INDIM / 16;   // 16 chunks
#pragma unroll 1
    for (int c = 0; c < NC; ++c) {
        float* Sx = sm[c & 1][0];
        float* S1 = sm[c & 1][1];
        float* Sa = sm[c & 1][2];
        float* Sb = sm[c & 1][3];
        // store prefetched chunk
        Sx[(kq*4+0)*32 + row] = xv.x;  Sx[(kq*4+1)*32 + row] = xv.y;
        Sx[(kq*4+2)*32 + row] = xv.z;  Sx[(kq*4+3)*32 + row] = xv.w;
        S1[(kq*4+0)*32 + row] = w1v.x; S1[(kq*4+1)*32 + row] = w1v.y;
        S1[(kq*4+2)*32 + row] = w1v.z; S1[(kq*4+3)*32 + row] = w1v.w;
        Sa[(kq*4+0)*32 + row] = wav.x; Sa[(kq*4+1)*32 + row] = wav.y;
        Sa[(kq*4+2)*32 + row] = wav.z; Sa[(kq*4+3)*32 + row] = wav.w;
        Sb[(kq*4+0)*32 + row] = wbv.x; Sb[(kq*4+1)*32 + row] = wbv.y;
        Sb[(kq*4+2)*32 + row] = wbv.z; Sb[(kq*4+3)*32 + row] = wbv.w;
        __syncthreads();

        if (c + 1 < NC) {
            const int ko = (c + 1) * 16;
            xv  = *(const float4*)(Xg  + ko);
            w1v = *(const float4*)(W1g + ko);
            wav = *(const float4*)(Wag + ko);
            wbv = *(const float4*)(Wbg + ko);
        }

        const float* Xp = sm[c & 1][0];
        const float* P1 = sm[c & 1][1];
        const float* Pa = sm[c & 1][2];
        const float* Pb = sm[c & 1][3];
#pragma unroll
        for (int kk = 0; kk < 16; kk++) {
            float2 a = *(const float2*)&Xp[kk * 32 + tym * 2];
            ulonglong2 b1v = *(const ulonglong2*)&P1[kk * 32 + txn * 4];
            ulonglong2 bav = *(const ulonglong2*)&Pa[kk * 32 + txn * 4];
            ulonglong2 bbv = *(const ulonglong2*)&Pb[kk * 32 + txn * 4];
            const u64 a0 = dup2(a.x), a1 = dup2(a.y);
            ac1[0][0] = ffma2(a0, b1v.x, ac1[0][0]); ac1[0][1] = ffma2(a0, b1v.y, ac1[0][1]);
            ac1[1][0] = ffma2(a1, b1v.x, ac1[1][0]); ac1[1][1] = ffma2(a1, b1v.y, ac1[1][1]);
            aca[0][0] = ffma2(a0, bav.x, aca[0][0]); aca[0][1] = ffma2(a0, bav.y, aca[0][1]);
            aca[1][0] = ffma2(a1, bav.x, aca[1][0]); aca[1][1] = ffma2(a1, bav.y, aca[1][1]);
            acb[0][0] = ffma2(a0, bbv.x, acb[0][0]); acb[0][1] = ffma2(a0, bbv.y, acb[0][1]);
            acb[1][0] = ffma2(a1, bbv.x, acb[1][0]); acb[1][1] = ffma2(a1, bbv.y, acb[1][1]);
        }
        __syncthreads();
    }

    // ---- epilogues ----
    const int n = n0 + txn * 4;
    const float4 qb  = *(const float4*)(b1  + n);
    const float4 qg  = *(const float4*)(gam + n);
    const float4 qbt = *(const float4*)(bet + n);
    const float4 qm  = *(const float4*)(mean + n);
    const float4 qv  = *(const float4*)(var + n);
    const float4 qs  = *(const float4*)(bs1 + n);
    const float* pb  = &qb.x;  const float* pg = &qg.x;
    const float* pbt = &qbt.x; const float* pm = &qm.x;
    const float* pv  = &qv.x;  const float* ps = &qs.x;

#pragma unroll
    for (int r = 0; r < 2; r++) {
        const int m = m0 + tym * 2 + r;
        float h[4], av[4], cv[4];
        unpack2(ac1[r][0], h[0], h[1]);  unpack2(ac1[r][1], h[2], h[3]);
        unpack2(aca[r][0], av[0], av[1]); unpack2(aca[r][1], av[2], av[3]);
        unpack2(acb[r][0], cv[0], cv[1]); unpack2(acb[r][1], cv[2], cv[3]);
#pragma unroll
        for (int c2 = 0; c2 < 4; c2++) {
            float v2 = h[c2] + pb[c2];
            v2 = pg[c2] * (v2 - pm[c2]) * rsqrtf(pv[c2] + 1e-5f) + pbt[c2];
            h[c2] = fmaxf(v2, 0.f);
            cv[c2] += ps[c2];
        }
        *(float4*)(g_H + (size_t)m * HIDD + n) = make_float4(h[0], h[1], h[2], h[3]);
        *(float4*)(g_A + (size_t)m * HIDD + n) = make_float4(av[0], av[1], av[2], av[3]);
        *(float4*)(g_C + (size_t)m * HIDD + n) = make_float4(cv[0], cv[1], cv[2], cv[3]);
    }
}

// ============================================================
// Single-matrix 32x32 GEMM tile (used for H2), 128 threads,
// microtile 2m x 4n, K chunks of 16, double-buffered.
// Out = relu(X@W^T + p0)
// ============================================================
__device__ __forceinline__ void gemm32_relu(
    const float* __restrict__ X, const float* __restrict__ W,
    float* __restrict__ Out, int N, int K, int m0, int n0,
    const float* __restrict__ p0, float* sm)
{
    float* Xs = sm;          // 2 * 512
    float* Ws = sm + 1024;   // 2 * 512

    const int t   = threadIdx.x;
    const int txn = t & 7;
    const int tym = t >> 3;
    const int row = t & 31;
    const int kq  = t >> 5;

    const float* Xg = X + (size_t)(m0 + row) * K + kq * 4;
    const float* Wg = W + (size_t)(n0 + row) * K + kq * 4;

    u64 acc[2][2] = {{0ull, 0ull}, {0ull, 0ull}};

    float4 xv = *(const float4*)(Xg);
    float4 wv = *(const float4*)(Wg);

    const int NC = K / 16;
#pragma unroll 1
    for (int c = 0; c < NC; ++c) {
        float* Sx = Xs + (c & 1) * 512;
        float* Sw = Ws + (c & 1) * 512;
        Sx[(kq*4+0)*32 + row] = xv.x; Sx[(kq*4+1)*32 + row] = xv.y;
        Sx[(kq*4+2)*32 + row] = xv.z; Sx[(kq*4+3)*32 + row] = xv.w;
        Sw[(kq*4+0)*32 + row] = wv.x; Sw[(kq*4+1)*32 + row] = wv.y;
        Sw[(kq*4+2)*32 + row] = wv.z; Sw[(kq*4+3)*32 + row] = wv.w;
        __syncthreads();

        if (c + 1 < NC) {
            const int ko = (c + 1) * 16;
            xv = *(const float4*)(Xg + ko);
            wv = *(const float4*)(Wg + ko);
        }

        const float* Xp = Xs + (c & 1) * 512;
        const float* Wp = Ws + (c & 1) * 512;
#pragma unroll
        for (int kk = 0; kk < 16; kk++) {
            float2 a = *(const float2*)&Xp[kk * 32 + tym * 2];
            ulonglong2 b = *(const ulonglong2*)&Wp[kk * 32 + txn * 4];
            const u64 a0 = dup2(a.x), a1 = dup2(a.y);
            acc[0][0] = ffma2(a0, b.x, acc[0][0]); acc[0][1] = ffma2(a0, b.y, acc[0][1]);
            acc[1][0] = ffma2(a1, b.x, acc[1][0]); acc[1][1] = ffma2(a1, b.y, acc[1][1]);
        }
        __syncthreads();
    }

    const int n = n0 + txn * 4;
    const float4 q0 = *(const float4*)(p0 + n);
    const float* bias = &q0.x;
#pragma unroll
    for (int r = 0; r < 2; r++) {
        float v[4];
        unpack2(acc[r][0], v[0], v[1]);
        unpack2(acc[r][1], v[2], v[3]);
#pragma unroll
        for (int c2 = 0; c2 < 4; c2++) v[c2] = fmaxf(v[c2] + bias[c2], 0.f);
        *(float4*)(Out + (size_t)(m0 + tym * 2 + r) * N + n) =
            make_float4(v[0], v[1], v[2], v[3]);
    }
}

// ============================================================
// Launch 2: blocks [0,128) = H2 = relu(H @ W2^T + b2), 32x32 tiles;
//           blocks [128,264) = similarity tiles (upper triangle).
// ============================================================
__global__ __launch_bounds__(128)
void k_simh2(const float* __restrict__ W2, const float* __restrict__ b2,
             const float* __restrict__ ws2, const float* __restrict__ bs2p,
             float* __restrict__ out_sim)
{
    __shared__ __align__(16) float sm[4160];

    if (blockIdx.x < 128) {
        const int idx = blockIdx.x;
        const int m0 = (idx >> 3) * 32;   // 16 m-tiles
        const int n0 = (idx & 7) * 32;    // 8 n-tiles
        gemm32_relu(g_H, W2, g_H2, HID2, HIDD, m0, n0, b2, sm);
        return;
    }

    // ---- similarity tile ----
    float* As = sm;          // 2 * 32 * 32
    float* Cs = sm + 2048;   // 2 * 32 * 32
    float* Ws = sm + 4096;   // 2 * 32

    // decode upper-triangle tile (bi <= bj)
    int rb = blockIdx.x - 128, bi = 0;
    while (rb >= 16 - bi) { rb -= 16 - bi; ++bi; }
    const int bj = bi + rb;
    const int i0 = bi * 32, j0 = bj * 32;

    const int t  = threadIdx.x;
    const int tx = t & 7;     // j quad
    const int ty = t >> 3;    // i pair

    const int lrow = t & 31;
    const int lkq  = t >> 5;  // 0..3 (handles kq and kq+4)

    const float* Ag = g_A + (size_t)(i0 + lrow) * HIDD;
    const float* Cg = g_C + (size_t)(j0 + lrow) * HIDD;

    // load chunk 0
    {
        float4 a0 = *(const float4*)(Ag + lkq * 4);
        float4 a1 = *(const float4*)(Ag + (lkq + 4) * 4);
        float4 c0 = *(const float4*)(Cg + lkq * 4);
        float4 c1 = *(const float4*)(Cg + (lkq + 4) * 4);
        As[(lkq*4+0)*32 + lrow] = a0.x; As[(lkq*4+1)*32 + lrow] = a0.y;
        As[(lkq*4+2)*32 + lrow] = a0.z; As[(lkq*4+3)*32 + lrow] = a0.w;
        As[((lkq+4)*4+0)*32 + lrow] = a1.x; As[((lkq+4)*4+1)*32 + lrow] = a1.y;
        As[((lkq+4)*4+2)*32 + lrow] = a1.z; As[((lkq+4)*4+3)*32 + lrow] = a1.w;
        Cs[(lkq*4+0)*32 + lrow] = c0.x; Cs[(lkq*4+1)*32 + lrow] = c0.y;
        Cs[(lkq*4+2)*32 + lrow] = c0.z; Cs[(lkq*4+3)*32 + lrow] = c0.w;
        Cs[((lkq+4)*4+0)*32 + lrow] = c1.x; Cs[((lkq+4)*4+1)*32 + lrow] = c1.y;
        Cs[((lkq+4)*4+2)*32 + lrow] = c1.z; Cs[((lkq+4)*4+3)*32 + lrow] = c1.w;
        if (t < 8) *(float4*)&Ws[t * 4] = *(const float4*)(ws2 + t * 4);
    }
    __syncthreads();

    float acc[2][4];
#pragma unroll
    for (int r = 0; r < 2; r++)
#pragma unroll
        for (int c = 0; c < 4; c++) acc[r][c] = 0.f;

#pragma unroll 1
    for (int ch = 0; ch < 16; ++ch) {
        const float* Ab = As + (ch & 1) * 1024;
        const float* Cb = Cs + (ch & 1) * 1024;
        const float* Wb = Ws + (ch & 1) * 32;

        float4 a0, a1, c0, c1, wv;
        const bool pf = (ch + 1 < 16);
        if (pf) {
            const int k0 = (ch + 1) << 5;
            a0 = *(const float4*)(Ag + k0 + lkq * 4);
            a1 = *(const float4*)(Ag + k0 + (lkq + 4) * 4);
            c0 = *(const float4*)(Cg + k0 + lkq * 4);
            c1 = *(const float4*)(Cg + k0 + (lkq + 4) * 4);
            if (t < 8) wv = *(const float4*)(ws2 + k0 + t * 4);
        }

#pragma unroll
        for (int kk = 0; kk < 32; kk++) {
            float2 a  = *(const float2*)&Ab[kk * 32 + ty * 2];
            float4 cc = *(const float4*)&Cb[kk * 32 + tx * 4];
            const float w = Wb[kk];
            acc[0][0] += fmaxf(a.x + cc.x, 0.f) * w;
            acc[0][1] += fmaxf(a.x + cc.y, 0.f) * w;
            acc[0][2] += fmaxf(a.x + cc.z, 0.f) * w;
            acc[0][3] += fmaxf(a.x + cc.w, 0.f) * w;
            acc[1][0] += fmaxf(a.y + cc.x, 0.f) * w;
            acc[1][1] += fmaxf(a.y + cc.y, 0.f) * w;
            acc[1][2] += fmaxf(a.y + cc.z, 0.f) * w;
            acc[1][3] += fmaxf(a.y + cc.w, 0.f) * w;
        }

        if (pf) {
            float* An = As + ((ch + 1) & 1) * 1024;
            float* Cn = Cs + ((ch + 1) & 1) * 1024;
            An[(lkq*4+0)*32 + lrow] = a0.x; An[(lkq*4+1)*32 + lrow] = a0.y;
            An[(lkq*4+2)*32 + lrow] = a0.z; An[(lkq*4+3)*32 + lrow] = a0.w;
            An[((lkq+4)*4+0)*32 + lrow] = a1.x; An[((lkq+4)*4+1)*32 + lrow] = a1.y;
            An[((lkq+4)*4+2)*32 + lrow] = a1.z; An[((lkq+4)*4+3)*32 + lrow] = a1.w;
            Cn[(lkq*4+0)*32 + lrow] = c0.x; Cn[(lkq*4+1)*32 + lrow] = c0.y;
            Cn[(lkq*4+2)*32 + lrow] = c0.z; Cn[(lkq*4+3)*32 + lrow] = c0.w;
            Cn[((lkq+4)*4+0)*32 + lrow] = c1.x; Cn[((lkq+4)*4+1)*32 + lrow] = c1.y;
            Cn[((lkq+4)*4+2)*32 + lrow] = c1.z; Cn[((lkq+4)*4+3)*32 + lrow] = c1.w;
            if (t < 8) *(float4*)&Ws[((ch + 1) & 1) * 32 + t * 4] = wv;
        }
        __syncthreads();
    }

    const float bs2 = *bs2p;
#pragma unroll
    for (int r = 0; r < 2; r++) {
#pragma unroll
        for (int c = 0; c < 4; c++) {
            const int i = i0 + ty * 2 + r;
            const int j = j0 + tx * 4 + c;
            if (i < j) {
                const float s = 1.f / (1.f + __expf(-(acc[r][c] + bs2)));
                out_sim[(size_t)i * BATCH + j] = s;
                out_sim[(size_t)j * BATCH + i] = s;
            } else if (i == j) {
                out_sim[(size_t)i * BATCH + j] = 0.f;
            }
        }
    }
}

// ============================================================
// Launch 3: scores + softmax (reads g_H2), one warp per row.
// ============================================================
__global__ __launch_bounds__(128)
void k_scores(const float* __restrict__ W3, const float* __restrict__ b3,
              float* __restrict__ out_probs, float* __restrict__ out_scores)
{
    const int warp = threadIdx.x >> 5;
    const int lane = threadIdx.x & 31;
    const int row  = blockIdx.x * 4 + warp;
    const float* h = g_H2 + (size_t)row * HID2;

    float acc[PAT];
#pragma unroll
    for (int p = 0; p < PAT; p++) acc[p] = 0.f;

    for (int k = lane; k < HID2; k += 32) {
        const float hv = h[k];
#pragma unroll
        for (int p = 0; p < PAT; p++) acc[p] += hv * W3[p * HID2 + k];
    }
#pragma unroll
    for (int p = 0; p < PAT; p++) {
#pragma unroll
        for (int off = 16; off; off >>= 1)
            acc[p] += __shfl_xor_sync(0xFFFFFFFFu, acc[p], off);
    }
    if (lane == 0) {
        float s[PAT], e[PAT];
        float mx = -1e30f;
#pragma unroll
        for (int p = 0; p < PAT; p++) { s[p] = acc[p] + b3[p]; mx = fmaxf(mx, s[p]); }
        float sum = 0.f;
#pragma unroll
        for (int p = 0; p < PAT; p++) { e[p] = __expf(s[p] - mx); sum += e[p]; }
        const float inv = 1.f / sum;
#pragma unroll
        for (int p = 0; p < PAT; p++) {
            out_scores[row * PAT + p] = s[p];
            out_probs [row * PAT + p] = e[p] * inv;
        }
    }
}

// ============================================================
extern "C" void kernel_launch(void* const* d_in, const int* in_sizes, int n_in,
                              void* d_out, int out_size)
{
    const float* x    = (const float*)d_in[0];
    const float* W1   = (const float*)d_in[1];
    const float* b1   = (const float*)d_in[2];
    const float* gam  = (const float*)d_in[3];
    const float* bet  = (const float*)d_in[4];
    const float* mean = (const float*)d_in[5];
    const float* var  = (const float*)d_in[6];
    const float* W2   = (const float*)d_in[7];
    const float* b2   = (const float*)d_in[8];
    const float* W3   = (const float*)d_in[9];
    const float* b3   = (const float*)d_in[10];
    const float* Wa   = (const float*)d_in[11];
    const float* Wb   = (const float*)d_in[12];
    const float* bs1  = (const float*)d_in[13];
    const float* ws2  = (const float*)d_in[14];
    const float* bs2  = (const float*)d_in[15];

    float* out        = (float*)d_out;
    float* out_probs  = out;
    float* out_scores = out + BATCH * PAT;
    float* out_sim    = out + 2 * BATCH * PAT;

    // 1) fused H, A, C projections (256 CTAs, shared X tile)
    k_proj3<<<dim3(16, 16), 128>>>(x, W1, b1, gam, bet, mean, var, Wa, Wb, bs1);
    // 2) H2 (128 CTAs) + sim (136 CTAs) in one launch
    k_simh2<<<264, 128>>>(W2, b2, ws2, bs2, out_sim);
    // 3) scores + softmax
    k_scores<<<BATCH / 4, 128>>>(W3, b3, out_probs, out_scores);
}

// round 6
// speedup vs baseline: 1.0337x; 1.0337x over previous
#include <cuda_runtime.h>
#include <math.h>

#define BATCH 512
#define INDIM 256
#define HIDD  512
#define HID2  256
#define PAT   10

typedef unsigned long long u64;

// -------- scratch (no allocations allowed) --------
__device__ __align__(128) float g_H [BATCH * HIDD];
__device__ __align__(128) float g_H2[BATCH * HID2];
__device__ __align__(128) float g_A [BATCH * HIDD];
__device__ __align__(128) float g_C [BATCH * HIDD];

// ---------- packed f32x2 helpers (sm_103a) ----------
__device__ __forceinline__ u64 pack2(float lo, float hi) {
    u64 r; asm("mov.b64 %0, {%1, %2};" : "=l"(r) : "f"(lo), "f"(hi)); return r;
}
__device__ __forceinline__ void unpack2(u64 v, float& lo, float& hi) {
    asm("mov.b64 {%0, %1}, %2;" : "=f"(lo), "=f"(hi) : "l"(v));
}
__device__ __forceinline__ u64 ffma2(u64 a, u64 b, u64 c) {
    u64 d; asm("fma.rn.f32x2 %0, %1, %2, %3;" : "=l"(d) : "l"(a), "l"(b), "l"(c)); return d;
}
__device__ __forceinline__ u64 dup2(float v) { return pack2(v, v); }

// ============================================================
// Split-K(2) GEMM tile: Out[m][n] = sum_k X[m][k]*W[n][k] (+epilogue)
// 256 threads = 2 independent 128-thread K-groups; group g covers
// K range [g*K/2, (g+1)*K/2) with the proven 64m x 32n / 4x4-microtile
// double-buffered loop (1 barrier per 16-deep chunk; barriers are
// CTA-wide but both groups run identical trip counts, so lockstep).
// One end-of-loop combine: group1 -> smem ex, group0 adds + epilogue.
// smem: per-group 3072 floats (Xs 2x1024, Wt 2x512), ex 2048 floats.
// mode 0: BN(+b1)+ReLU ; 1: none ; 2: +p0 ; 3: relu(+p0)
// ============================================================
__device__ __forceinline__ void gemm_sk2(
    const float* __restrict__ X, const float* __restrict__ W,
    float* __restrict__ Out, int N, int Kstr, int m0, int n0, int mode,
    const float* __restrict__ p0, const float* __restrict__ p1,
    const float* __restrict__ p2, const float* __restrict__ p3,
    const float* __restrict__ p4, float* sm, float* ex)
{
    const int tid = threadIdx.x;
    const int g   = tid >> 7;      // K-group 0/1
    const int t   = tid & 127;

    float* Xs = sm + g * 3072;    // 2 * 16 * 64
    float* Wt = Xs + 2048;        // 2 * 16 * 32

    const int txn = t & 7;        // n quad (4 cols)
    const int tym = t >> 3;       // m quad (4 rows), 0..15

    const int xrow = t & 63;      // X loader row
    const int xkq  = t >> 6;      // 0..1 (handles kq and kq+2)
    const int wrow = t & 31;      // W loader row
    const int wkq  = t >> 5;      // 0..3

    const int kb = g * (Kstr >> 1);
    const float* Xg = X + (size_t)(m0 + xrow) * Kstr + kb;
    const float* Wg = W + (size_t)(n0 + wrow) * Kstr + kb;

    // ---- load chunk 0 ----
    {
        float4 v0 = *(const float4*)(Xg + xkq * 4);
        float4 v1 = *(const float4*)(Xg + (xkq + 2) * 4);
        float4 wv = *(const float4*)(Wg + wkq * 4);
        Xs[(xkq*4+0)*64 + xrow] = v0.x; Xs[(xkq*4+1)*64 + xrow] = v0.y;
        Xs[(xkq*4+2)*64 + xrow] = v0.z; Xs[(xkq*4+3)*64 + xrow] = v0.w;
        Xs[((xkq+2)*4+0)*64 + xrow] = v1.x; Xs[((xkq+2)*4+1)*64 + xrow] = v1.y;
        Xs[((xkq+2)*4+2)*64 + xrow] = v1.z; Xs[((xkq+2)*4+3)*64 + xrow] = v1.w;
        Wt[(wkq*4+0)*32 + wrow] = wv.x; Wt[(wkq*4+1)*32 + wrow] = wv.y;
        Wt[(wkq*4+2)*32 + wrow] = wv.z; Wt[(wkq*4+3)*32 + wrow] = wv.w;
    }
    __syncthreads();

    u64 acc[4][2];
#pragma unroll
    for (int r = 0; r < 4; r++) { acc[r][0] = 0ull; acc[r][1] = 0ull; }

    const int NC = Kstr >> 5;     // chunks of 16 over K/2
#pragma unroll 1
    for (int c = 0; c < NC; ++c) {
        const float* Xb = Xs + (c & 1) * 1024;
        const float* Wb = Wt + (c & 1) * 512;

        float4 v0, v1, wv;
        const bool pf = (c + 1 < NC);
        if (pf) {
            const int k0 = (c + 1) << 4;
            v0 = *(const float4*)(Xg + k0 + xkq * 4);
            v1 = *(const float4*)(Xg + k0 + (xkq + 2) * 4);
            wv = *(const float4*)(Wg + k0 + wkq * 4);
        }

#pragma unroll
        for (int kk = 0; kk < 16; kk++) {
            float4 a = *(const float4*)&Xb[kk * 64 + (tym << 2)];
            ulonglong2 b = *(const ulonglong2*)&Wb[kk * 32 + (txn << 2)];
            const u64 a0 = dup2(a.x), a1 = dup2(a.y);
            const u64 a2 = dup2(a.z), a3 = dup2(a.w);
            acc[0][0] = ffma2(a0, b.x, acc[0][0]); acc[0][1] = ffma2(a0, b.y, acc[0][1]);
            acc[1][0] = ffma2(a1, b.x, acc[1][0]); acc[1][1] = ffma2(a1, b.y, acc[1][1]);
            acc[2][0] = ffma2(a2, b.x, acc[2][0]); acc[2][1] = ffma2(a2, b.y, acc[2][1]);
            acc[3][0] = ffma2(a3, b.x, acc[3][0]); acc[3][1] = ffma2(a3, b.y, acc[3][1]);
        }

        if (pf) {
            float* Xn = Xs + ((c + 1) & 1) * 1024;
            float* Wn = Wt + ((c + 1) & 1) * 512;
            Xn[(xkq*4+0)*64 + xrow] = v0.x; Xn[(xkq*4+1)*64 + xrow] = v0.y;
            Xn[(xkq*4+2)*64 + xrow] = v0.z; Xn[(xkq*4+3)*64 + xrow] = v0.w;
            Xn[((xkq+2)*4+0)*64 + xrow] = v1.x; Xn[((xkq+2)*4+1)*64 + xrow] = v1.y;
            Xn[((xkq+2)*4+2)*64 + xrow] = v1.z; Xn[((xkq+2)*4+3)*64 + xrow] = v1.w;
            Wn[(wkq*4+0)*32 + wrow] = wv.x; Wn[(wkq*4+1)*32 + wrow] = wv.y;
            Wn[(wkq*4+2)*32 + wrow] = wv.z; Wn[(wkq*4+3)*32 + wrow] = wv.w;
        }
        __syncthreads();
    }

    // ---- unpack partials ----
    float va[4][4];
#pragma unroll
    for (int r = 0; r < 4; r++) {
        unpack2(acc[r][0], va[r][0], va[r][1]);
        unpack2(acc[r][1], va[r][2], va[r][3]);
    }

    // ---- single combine: group1 -> ex, group0 adds ----
    if (g == 1) {
#pragma unroll
        for (int r = 0; r < 4; r++)
            *(float4*)&ex[(tym * 4 + r) * 32 + txn * 4] =
                make_float4(va[r][0], va[r][1], va[r][2], va[r][3]);
    }
    __syncthreads();
    if (g == 1) return;

#pragma unroll
    for (int r = 0; r < 4; r++) {
        float4 e = *(const float4*)&ex[(tym * 4 + r) * 32 + txn * 4];
        va[r][0] += e.x; va[r][1] += e.y; va[r][2] += e.z; va[r][3] += e.w;
    }

    // ---- epilogue ----
    const int n = n0 + txn * 4;
    float4 q0 = make_float4(0.f, 0.f, 0.f, 0.f), q1 = q0, q2 = q0, q3 = q0, q4 = q0;
    if (mode == 0) {
        q0 = *(const float4*)(p0 + n); q1 = *(const float4*)(p1 + n);
        q2 = *(const float4*)(p2 + n); q3 = *(const float4*)(p3 + n);
        q4 = *(const float4*)(p4 + n);
    } else if (mode == 2 || mode == 3) {
        q0 = *(const float4*)(p0 + n);
    }
    const float* bias = &q0.x;
    const float* gam  = &q1.x;
    const float* bet  = &q2.x;
    const float* mean = &q3.x;
    const float* var  = &q4.x;

#pragma unroll
    for (int r = 0; r < 4; r++) {
        float v[4];
#pragma unroll
        for (int c2 = 0; c2 < 4; c2++) {
            float v2 = va[r][c2];
            if (mode == 0) {
                v2 += bias[c2];
                v2 = gam[c2] * (v2 - mean[c2]) * rsqrtf(var[c2] + 1e-5f) + bet[c2];
                v2 = fmaxf(v2, 0.f);
            } else if (mode == 2) {
                v2 += bias[c2];
            } else if (mode == 3) {
                v2 = fmaxf(v2 + bias[c2], 0.f);
            }
            v[c2] = v2;
        }
        *(float4*)(Out + (size_t)(m0 + tym * 4 + r) * N + n) =
            make_float4(v[0], v[1], v[2], v[3]);
    }
}

// ============================================================
// Launch 1: three x-projections (H via BN+ReLU, A, C+bs1)
// grid (16 n-tiles, 8 m-tiles, 3 weights), 256 threads (split-K2).
// ============================================================
__global__ __launch_bounds__(256)
void k_proj(const float* __restrict__ x,
            const float* __restrict__ W1, const float* __restrict__ b1,
            const float* __restrict__ gam, const float* __restrict__ bet,
            const float* __restrict__ mean, const float* __restrict__ var,
            const float* __restrict__ Wa, const float* __restrict__ Wb,
            const float* __restrict__ bs1)
{
    __shared__ __align__(16) float sm[8192];   // 2*3072 bufs + 2048 ex
    float* ex = sm + 6144;
    const int m0 = blockIdx.y * 64;
    const int n0 = blockIdx.x * 32;
    const int z  = blockIdx.z;
    if (z == 0)
        gemm_sk2(x, W1, g_H, HIDD, INDIM, m0, n0, 0, b1, gam, bet, mean, var, sm, ex);
    else if (z == 1)
        gemm_sk2(x, Wa, g_A, HIDD, INDIM, m0, n0, 1,
                 nullptr, nullptr, nullptr, nullptr, nullptr, sm, ex);
    else
        gemm_sk2(x, Wb, g_C, HIDD, INDIM, m0, n0, 2,
                 bs1, nullptr, nullptr, nullptr, nullptr, sm, ex);
}

// ============================================================
// Launch 2: blocks [0,136) = similarity tiles (upper triangle),
//           blocks [136,200) = H2 = relu(H @ W2^T + b2) 64x32 tiles.
// 256 threads; both paths use 2-group split-K with one combine.
// sim: 32x32 pair tile, 2i x 4j micro-tile, per group K=256 in
// 8 chunks of 32, double-buffered.
// ============================================================
__global__ __launch_bounds__(256)
void k_simh2(const float* __restrict__ W2, const float* __restrict__ b2,
             const float* __restrict__ ws2, const float* __restrict__ bs2p,
             float* __restrict__ out_sim)
{
    __shared__ __align__(16) float sm[9344];

    if (blockIdx.x >= 136) {
        const int idx = blockIdx.x - 136;          // 0..63
        const int m0 = (idx >> 3) * 64;            // 8 m-tiles
        const int n0 = (idx & 7) * 32;             // 8 n-tiles
        gemm_sk2(g_H, W2, g_H2, HID2, HIDD, m0, n0, 3,
                 b2, nullptr, nullptr, nullptr, nullptr, sm, sm + 6144);
        return;
    }

    // ---- similarity tile ----
    const int tid = threadIdx.x;
    const int g   = tid >> 7;
    const int t   = tid & 127;

    float* As = sm + g * 4160;   // 2 * 32 * 32
    float* Cs = As + 2048;       // 2 * 32 * 32
    float* Ws = As + 4096;       // 2 * 32
    float* ex = sm + 8320;       // 1024 floats

    // decode upper-triangle tile (bi <= bj)
    int rb = blockIdx.x, bi = 0;
    while (rb >= 16 - bi) { rb -= 16 - bi; ++bi; }
    const int bj = bi + rb;
    const int i0 = bi * 32, j0 = bj * 32;

    const int tx = t & 7;     // j quad
    const int ty = t >> 3;    // i pair

    const int lrow = t & 31;
    const int lkq  = t >> 5;  // 0..3 (handles kq and kq+4)
    const int kb   = g * 256;

    const float* Ag = g_A + (size_t)(i0 + lrow) * HIDD + kb;
    const float* Cg = g_C + (size_t)(j0 + lrow) * HIDD + kb;
    const float* Wg = ws2 + kb;

    // ---- load chunk 0 ----
    {
        float4 a0 = *(const float4*)(Ag + lkq * 4);
        float4 a1 = *(const float4*)(Ag + (lkq + 4) * 4);
        float4 c0 = *(const float4*)(Cg + lkq * 4);
        float4 c1 = *(const float4*)(Cg + (lkq + 4) * 4);
        As[(lkq*4+0)*32 + lrow] = a0.x; As[(lkq*4+1)*32 + lrow] = a0.y;
        As[(lkq*4+2)*32 + lrow] = a0.z; As[(lkq*4+3)*32 + lrow] = a0.w;
        As[((lkq+4)*4+0)*32 + lrow] = a1.x; As[((lkq+4)*4+1)*32 + lrow] = a1.y;
        As[((lkq+4)*4+2)*32 + lrow] = a1.z; As[((lkq+4)*4+3)*32 + lrow] = a1.w;
        Cs[(lkq*4+0)*32 + lrow] = c0.x; Cs[(lkq*4+1)*32 + lrow] = c0.y;
        Cs[(lkq*4+2)*32 + lrow] = c0.z; Cs[(lkq*4+3)*32 + lrow] = c0.w;
        Cs[((lkq+4)*4+0)*32 + lrow] = c1.x; Cs[((lkq+4)*4+1)*32 + lrow] = c1.y;
        Cs[((lkq+4)*4+2)*32 + lrow] = c1.z; Cs[((lkq+4)*4+3)*32 + lrow] = c1.w;
        if (t < 8) *(float4*)&Ws[t * 4] = *(const float4*)(Wg + t * 4);
    }
    __syncthreads();

    float acc[2][4];
#pragma unroll
    for (int r = 0; r < 2; r++)
#pragma unroll
        for (int c = 0; c < 4; c++) acc[r][c] = 0.f;

#pragma unroll 1
    for (int ch = 0; ch < 8; ++ch) {          // 8 chunks of 32 k per group
        const float* Ab = As + (ch & 1) * 1024;
        const float* Cb = Cs + (ch & 1) * 1024;
        const float* Wb = Ws + (ch & 1) * 32;

        float4 a0, a1, c0, c1, wv;
        const bool pf = (ch + 1 < 8);
        if (pf) {
            const int k0 = (ch + 1) << 5;
            a0 = *(const float4*)(Ag + k0 + lkq * 4);
            a1 = *(const float4*)(Ag + k0 + (lkq + 4) * 4);
            c0 = *(const float4*)(Cg + k0 + lkq * 4);
            c1 = *(const float4*)(Cg + k0 + (lkq + 4) * 4);
            if (t < 8) wv = *(const float4*)(Wg + k0 + t * 4);
        }

#pragma unroll
        for (int kk = 0; kk < 32; kk++) {
            float2 a  = *(const float2*)&Ab[kk * 32 + ty * 2];
            float4 cc = *(const float4*)&Cb[kk * 32 + tx * 4];
            const float w = Wb[kk];
            acc[0][0] += fmaxf(a.x + cc.x, 0.f) * w;
            acc[0][1] += fmaxf(a.x + cc.y, 0.f) * w;
            acc[0][2] += fmaxf(a.x + cc.z, 0.f) * w;
            acc[0][3] += fmaxf(a.x + cc.w, 0.f) * w;
            acc[1][0] += fmaxf(a.y + cc.x, 0.f) * w;
            acc[1][1] += fmaxf(a.y + cc.y, 0.f) * w;
            acc[1][2] += fmaxf(a.y + cc.z, 0.f) * w;
            acc[1][3] += fmaxf(a.y + cc.w, 0.f) * w;
        }

        if (pf) {
            float* An = As + ((ch + 1) & 1) * 1024;
            float* Cn = Cs + ((ch + 1) & 1) * 1024;
            An[(lkq*4+0)*32 + lrow] = a0.x; An[(lkq*4+1)*32 + lrow] = a0.y;
            An[(lkq*4+2)*32 + lrow] = a0.z; An[(lkq*4+3)*32 + lrow] = a0.w;
            An[((lkq+4)*4+0)*32 + lrow] = a1.x; An[((lkq+4)*4+1)*32 + lrow] = a1.y;
            An[((lkq+4)*4+2)*32 + lrow] = a1.z; An[((lkq+4)*4+3)*32 + lrow] = a1.w;
            Cn[(lkq*4+0)*32 + lrow] = c0.x; Cn[(lkq*4+1)*32 + lrow] = c0.y;
            Cn[(lkq*4+2)*32 + lrow] = c0.z; Cn[(lkq*4+3)*32 + lrow] = c0.w;
            Cn[((lkq+4)*4+0)*32 + lrow] = c1.x; Cn[((lkq+4)*4+1)*32 + lrow] = c1.y;
            Cn[((lkq+4)*4+2)*32 + lrow] = c1.z; Cn[((lkq+4)*4+3)*32 + lrow] = c1.w;
            if (t < 8) *(float4*)&Ws[((ch + 1) & 1) * 32 + t * 4] = wv;
        }
        __syncthreads();
    }

    // ---- single combine: group1 -> ex, group0 adds ----
    if (g == 1) {
        *(float4*)&ex[t * 8]     = make_float4(acc[0][0], acc[0][1], acc[0][2], acc[0][3]);
        *(float4*)&ex[t * 8 + 4] = make_float4(acc[1][0], acc[1][1], acc[1][2], acc[1][3]);
    }
    __syncthreads();
    if (g == 1) return;
    {
        float4 e0 = *(const float4*)&ex[t * 8];
        float4 e1 = *(const float4*)&ex[t * 8 + 4];
        acc[0][0] += e0.x; acc[0][1] += e0.y; acc[0][2] += e0.z; acc[0][3] += e0.w;
        acc[1][0] += e1.x; acc[1][1] += e1.y; acc[1][2] += e1.z; acc[1][3] += e1.w;
    }

    const float bs2 = *bs2p;
#pragma unroll
    for (int r = 0; r < 2; r++) {
#pragma unroll
        for (int c = 0; c < 4; c++) {
            const int i = i0 + ty * 2 + r;
            const int j = j0 + tx * 4 + c;
            if (i < j) {
                const float s = 1.f / (1.f + __expf(-(acc[r][c] + bs2)));
                out_sim[(size_t)i * BATCH + j] = s;
                out_sim[(size_t)j * BATCH + i] = s;
            } else if (i == j) {
                out_sim[(size_t)i * BATCH + j] = 0.f;
            }
        }
    }
}

// ============================================================
// Launch 3: scores + softmax (reads g_H2), one warp per row.
// ============================================================
__global__ __launch_bounds__(128)
void k_scores(const float* __restrict__ W3, const float* __restrict__ b3,
              float* __restrict__ out_probs, float* __restrict__ out_scores)
{
    const int warp = threadIdx.x >> 5;
    const int lane = threadIdx.x & 31;
    const int row  = blockIdx.x * 4 + warp;
    const float* h = g_H2 + (size_t)row * HID2;

    float acc[PAT];
#pragma unroll
    for (int p = 0; p < PAT; p++) acc[p] = 0.f;

    for (int k = lane; k < HID2; k += 32) {
        const float hv = h[k];
#pragma unroll
        for (int p = 0; p < PAT; p++) acc[p] += hv * W3[p * HID2 + k];
    }
#pragma unroll
    for (int p = 0; p < PAT; p++) {
#pragma unroll
        for (int off = 16; off; off >>= 1)
            acc[p] += __shfl_xor_sync(0xFFFFFFFFu, acc[p], off);
    }
    if (lane == 0) {
        float s[PAT], e[PAT];
        float mx = -1e30f;
#pragma unroll
        for (int p = 0; p < PAT; p++) { s[p] = acc[p] + b3[p]; mx = fmaxf(mx, s[p]); }
        float sum = 0.f;
#pragma unroll
        for (int p = 0; p < PAT; p++) { e[p] = __expf(s[p] - mx); sum += e[p]; }
        const float inv = 1.f / sum;
#pragma unroll
        for (int p = 0; p < PAT; p++) {
            out_scores[row * PAT + p] = s[p];
            out_probs [row * PAT + p] = e[p] * inv;
        }
    }
}

// ============================================================
extern "C" void kernel_launch(void* const* d_in, const int* in_sizes, int n_in,
                              void* d_out, int out_size)
{
    const float* x    = (const float*)d_in[0];
    const float* W1   = (const float*)d_in[1];
    const float* b1   = (const float*)d_in[2];
    const float* gam  = (const float*)d_in[3];
    const float* bet  = (const float*)d_in[4];
    const float* mean = (const float*)d_in[5];
    const float* var  = (const float*)d_in[6];
    const float* W2   = (const float*)d_in[7];
    const float* b2   = (const float*)d_in[8];
    const float* W3   = (const float*)d_in[9];
    const float* b3   = (const float*)d_in[10];
    const float* Wa   = (const float*)d_in[11];
    const float* Wb   = (const float*)d_in[12];
    const float* bs1  = (const float*)d_in[13];
    const float* ws2  = (const float*)d_in[14];
    const float* bs2  = (const float*)d_in[15];

    float* out        = (float*)d_out;
    float* out_probs  = out;
    float* out_scores = out + BATCH * PAT;
    float* out_sim    = out + 2 * BATCH * PAT;

    // 1) H, A, C projections (384 CTAs x 256 threads, split-K2)
    k_proj<<<dim3(16, 8, 3), 256>>>(x, W1, b1, gam, bet, mean, var, Wa, Wb, bs1);
    // 2) sim (136 CTAs) + H2 (64 CTAs), 256 threads, split-K2
    k_simh2<<<200, 256>>>(W2, b2, ws2, bs2, out_sim);
    // 3) scores + softmax
    k_scores<<<BATCH / 4, 128>>>(W3, b3, out_probs, out_scores);
}